// round 1
// baseline (speedup 1.0000x reference)
#include <cuda_runtime.h>
#include <cstdint>

#define EMB 128
#define NMAX 50000

// ---------------- scratch (static device globals; no allocation) ----------------
__device__ float g_aggr[NMAX * EMB];          // 25.6 MB
__device__ float g_h1[NMAX * 2 * EMB];        // 51.2 MB
__device__ float g_stat[768];                 // sum1[256] sq1[256] sum2[128] sq2[128]
__device__ float g_scale1[2 * EMB], g_shift1[2 * EMB];
__device__ float g_scale2[EMB],     g_shift2[EMB];
__device__ int   g_is64;

// ---------------- zero scratch each replay (graph-capturable kernel) ------------
__global__ void zero_kernel(int n) {
    int i = blockIdx.x * blockDim.x + threadIdx.x;
    if (i < n) g_aggr[i] = 0.0f;
    if (blockIdx.x == 0) {
        for (int j = threadIdx.x; j < 768; j += blockDim.x) g_stat[j] = 0.0f;
    }
}

// ---------------- detect edge_index dtype (int64 vs silently-downcast int32) ----
__global__ void detect_kernel(const unsigned long long* __restrict__ p, int n_nodes) {
    if (threadIdx.x == 0) {
        int ok = 1;
        for (int i = 0; i < 64; i++)
            if (p[i] >= (unsigned long long)n_nodes) { ok = 0; break; }
        g_is64 = ok;
    }
}

// ---------------- edge message + scatter-add (1 warp = 1 edge) ------------------
__global__ __launch_bounds__(256) void edge_kernel(
    const float4* __restrict__ x4, const void* __restrict__ eiv,
    const float* __restrict__ ea, const float4* __restrict__ We4,
    const float4* __restrict__ be4, int E)
{
    __shared__ float4 sW[512];  // W_edge: 16 x 128 floats = 16 x 32 float4
    __shared__ float4 sB[32];   // b_edge
    int t = threadIdx.x;
    sW[t]       = We4[t];
    sW[t + 256] = We4[t + 256];
    if (t < 32) sB[t] = be4[t];
    __syncthreads();

    int warp = t >> 5, lane = t & 31;
    int e = blockIdx.x * 8 + warp;
    if (e >= E) return;

    int src, dst;
    if (g_is64) {
        const long long* pe = (const long long*)eiv;
        src = (int)pe[e]; dst = (int)pe[(size_t)E + e];
    } else {
        const int* pe = (const int*)eiv;
        src = pe[e]; dst = pe[(size_t)E + e];
    }

    float eav = (lane < 16) ? ea[(size_t)e * 16 + lane] : 0.0f;

    float4 acc = sB[lane];
#pragma unroll
    for (int k = 0; k < 16; k++) {
        float a = __shfl_sync(0xffffffffu, eav, k);
        float4 w = sW[k * 32 + lane];
        acc.x = fmaf(a, w.x, acc.x);
        acc.y = fmaf(a, w.y, acc.y);
        acc.z = fmaf(a, w.z, acc.z);
        acc.w = fmaf(a, w.w, acc.w);
    }
    float4 xv = x4[(size_t)src * 32 + lane];
    acc.x = fmaxf(acc.x + xv.x, 0.0f);
    acc.y = fmaxf(acc.y + xv.y, 0.0f);
    acc.z = fmaxf(acc.z + xv.z, 0.0f);
    acc.w = fmaxf(acc.w + xv.w, 0.0f);

    float* gp = g_aggr + (size_t)dst * EMB + lane * 4;
    asm volatile("red.global.add.v4.f32 [%0], {%1, %2, %3, %4};"
                 :: "l"(gp), "f"(acc.x), "f"(acc.y), "f"(acc.z), "f"(acc.w)
                 : "memory");
}

// ---------------- GEMM1: h1 = ((1+eps)*x + aggr) @ W1 + b1  (M x 256, K=128) ----
__global__ __launch_bounds__(256, 2) void gemm1_kernel(
    const float* __restrict__ X, const float* __restrict__ W,
    const float* __restrict__ bias, const float* __restrict__ epsp, int M)
{
    __shared__ float As[16][132];
    __shared__ float Bs[16][132];
    const float eps1 = 1.0f + *epsp;
    int t = threadIdx.x;
    int tx = t & 15, ty = t >> 4;
    int row0 = blockIdx.x * 128;
    int col0 = blockIdx.y * 128;
    float acc[8][8] = {};

    for (int kt = 0; kt < 128; kt += 16) {
#pragma unroll
        for (int l = 0; l < 2; l++) {
            int f = t + l * 256;
            int r = f >> 2, kq = (f & 3) * 4;
            int m = row0 + r;
            float4 v = make_float4(0.f, 0.f, 0.f, 0.f);
            if (m < M) {
                float4 xv = *(const float4*)(X + (size_t)m * 128 + kt + kq);
                float4 av = *(const float4*)(g_aggr + (size_t)m * 128 + kt + kq);
                v.x = fmaf(eps1, xv.x, av.x);
                v.y = fmaf(eps1, xv.y, av.y);
                v.z = fmaf(eps1, xv.z, av.z);
                v.w = fmaf(eps1, xv.w, av.w);
            }
            As[kq + 0][r] = v.x; As[kq + 1][r] = v.y;
            As[kq + 2][r] = v.z; As[kq + 3][r] = v.w;
        }
#pragma unroll
        for (int l = 0; l < 2; l++) {
            int f = t + l * 256;
            int kr = f >> 5, nc = (f & 31) * 4;
            *(float4*)&Bs[kr][nc] =
                *(const float4*)(W + (size_t)(kt + kr) * 256 + col0 + nc);
        }
        __syncthreads();
#pragma unroll
        for (int kk = 0; kk < 16; kk++) {
            float a0[8], b0[8];
            *(float4*)(a0)     = *(const float4*)&As[kk][ty * 4];
            *(float4*)(a0 + 4) = *(const float4*)&As[kk][64 + ty * 4];
            *(float4*)(b0)     = *(const float4*)&Bs[kk][tx * 4];
            *(float4*)(b0 + 4) = *(const float4*)&Bs[kk][64 + tx * 4];
#pragma unroll
            for (int i = 0; i < 8; i++)
#pragma unroll
                for (int j = 0; j < 8; j++)
                    acc[i][j] = fmaf(a0[i], b0[j], acc[i][j]);
        }
        __syncthreads();
    }
#pragma unroll
    for (int i = 0; i < 8; i++) {
        int m = row0 + ((i < 4) ? (ty * 4 + i) : (64 + ty * 4 + i - 4));
        if (m >= M) continue;
#pragma unroll
        for (int h = 0; h < 2; h++) {
            int c = col0 + h * 64 + tx * 4;
            float4 bb = *(const float4*)(bias + c);
            float4 o;
            o.x = acc[i][h * 4 + 0] + bb.x;
            o.y = acc[i][h * 4 + 1] + bb.y;
            o.z = acc[i][h * 4 + 2] + bb.z;
            o.w = acc[i][h * 4 + 3] + bb.w;
            *(float4*)(g_h1 + (size_t)m * 256 + c) = o;
        }
    }
}

// ---------------- column stats for h1 (256 cols) ---------------------------------
__global__ void stats1_kernel(int M) {
    int col = threadIdx.x;  // 256
    int r0 = blockIdx.x * 256;
    int r1 = min(r0 + 256, M);
    float s = 0.f, q = 0.f;
    for (int r = r0; r < r1; r++) {
        float v = g_h1[(size_t)r * 256 + col];
        s += v; q = fmaf(v, v, q);
    }
    atomicAdd(&g_stat[col], s);
    atomicAdd(&g_stat[256 + col], q);
}

// ---------------- column stats for h2 (128 cols, reads d_out) --------------------
__global__ void stats2_kernel(const float* __restrict__ H, int M) {
    int col = threadIdx.x;  // 128
    int r0 = blockIdx.x * 256;
    int r1 = min(r0 + 256, M);
    float s = 0.f, q = 0.f;
    for (int r = r0; r < r1; r++) {
        float v = H[(size_t)r * 128 + col];
        s += v; q = fmaf(v, v, q);
    }
    atomicAdd(&g_stat[512 + col], s);
    atomicAdd(&g_stat[640 + col], q);
}

// ---------------- finalize BN stats into fused scale/shift -----------------------
__global__ void finalize_kernel(const float* __restrict__ gam,
                                const float* __restrict__ bet,
                                int which, float invM)
{
    int c = threadIdx.x;
    float mu, msq;
    if (which == 0) { mu = g_stat[c] * invM;       msq = g_stat[256 + c] * invM; }
    else            { mu = g_stat[512 + c] * invM; msq = g_stat[640 + c] * invM; }
    float var = msq - mu * mu;
    float sc = gam[c] * rsqrtf(var + 1e-5f);
    float sh = bet[c] - mu * sc;
    if (which == 0) { g_scale1[c] = sc; g_shift1[c] = sh; }
    else            { g_scale2[c] = sc; g_shift2[c] = sh; }
}

// ---------------- GEMM2: out = relu(BN1(h1)) @ W2 + b2  (M x 128, K=256) ---------
__global__ __launch_bounds__(256, 2) void gemm2_kernel(
    const float* __restrict__ W, const float* __restrict__ bias,
    float* __restrict__ out, int M)
{
    __shared__ float As[16][132];
    __shared__ float Bs[16][132];
    int t = threadIdx.x;
    int tx = t & 15, ty = t >> 4;
    int row0 = blockIdx.x * 128;
    float acc[8][8] = {};

    for (int kt = 0; kt < 256; kt += 16) {
#pragma unroll
        for (int l = 0; l < 2; l++) {
            int f = t + l * 256;
            int r = f >> 2, kq = (f & 3) * 4;
            int m = row0 + r;
            float4 v = make_float4(0.f, 0.f, 0.f, 0.f);
            if (m < M) {
                float4 hv = *(const float4*)(g_h1 + (size_t)m * 256 + kt + kq);
                float4 sc = *(const float4*)(g_scale1 + kt + kq);
                float4 sh = *(const float4*)(g_shift1 + kt + kq);
                v.x = fmaxf(fmaf(hv.x, sc.x, sh.x), 0.0f);
                v.y = fmaxf(fmaf(hv.y, sc.y, sh.y), 0.0f);
                v.z = fmaxf(fmaf(hv.z, sc.z, sh.z), 0.0f);
                v.w = fmaxf(fmaf(hv.w, sc.w, sh.w), 0.0f);
            }
            As[kq + 0][r] = v.x; As[kq + 1][r] = v.y;
            As[kq + 2][r] = v.z; As[kq + 3][r] = v.w;
        }
#pragma unroll
        for (int l = 0; l < 2; l++) {
            int f = t + l * 256;
            int kr = f >> 5, nc = (f & 31) * 4;
            *(float4*)&Bs[kr][nc] =
                *(const float4*)(W + (size_t)(kt + kr) * 128 + nc);
        }
        __syncthreads();
#pragma unroll
        for (int kk = 0; kk < 16; kk++) {
            float a0[8], b0[8];
            *(float4*)(a0)     = *(const float4*)&As[kk][ty * 4];
            *(float4*)(a0 + 4) = *(const float4*)&As[kk][64 + ty * 4];
            *(float4*)(b0)     = *(const float4*)&Bs[kk][tx * 4];
            *(float4*)(b0 + 4) = *(const float4*)&Bs[kk][64 + tx * 4];
#pragma unroll
            for (int i = 0; i < 8; i++)
#pragma unroll
                for (int j = 0; j < 8; j++)
                    acc[i][j] = fmaf(a0[i], b0[j], acc[i][j]);
        }
        __syncthreads();
    }
#pragma unroll
    for (int i = 0; i < 8; i++) {
        int m = row0 + ((i < 4) ? (ty * 4 + i) : (64 + ty * 4 + i - 4));
        if (m >= M) continue;
#pragma unroll
        for (int h = 0; h < 2; h++) {
            int c = h * 64 + tx * 4;
            float4 bb = *(const float4*)(bias + c);
            float4 o;
            o.x = acc[i][h * 4 + 0] + bb.x;
            o.y = acc[i][h * 4 + 1] + bb.y;
            o.z = acc[i][h * 4 + 2] + bb.z;
            o.w = acc[i][h * 4 + 3] + bb.w;
            *(float4*)(out + (size_t)m * 128 + c) = o;
        }
    }
}

// ---------------- Threefry-2x32, key = (0, 42) -----------------------------------
__device__ __forceinline__ uint2 threefry2x32_042(uint32_t x0, uint32_t x1)
{
    const uint32_t k0 = 0u, k1 = 42u;
    const uint32_t k2 = k0 ^ k1 ^ 0x1BD11BDAu;
    x0 += k0; x1 += k1;
#define TF_R(r) { x0 += x1; x1 = __funnelshift_l(x1, x1, r); x1 ^= x0; }
    TF_R(13) TF_R(15) TF_R(26) TF_R(6)
    x0 += k1; x1 += k2 + 1u;
    TF_R(17) TF_R(29) TF_R(16) TF_R(24)
    x0 += k2; x1 += k0 + 2u;
    TF_R(13) TF_R(15) TF_R(26) TF_R(6)
    x0 += k0; x1 += k1 + 3u;
    TF_R(17) TF_R(29) TF_R(16) TF_R(24)
    x0 += k1; x1 += k2 + 4u;
    TF_R(13) TF_R(15) TF_R(26) TF_R(6)
    x0 += k2; x1 += k0 + 5u;
#undef TF_R
    return make_uint2(x0, x1);
}

// ---------------- outer BN + dropout (JAX partitionable threefry) ----------------
// bits[i] = out0 ^ out1 of threefry2x32(key=(0,42), counter=(i>>32, i&0xffffffff));
// u = bitcast((bits>>9)|0x3f800000) - 1;  keep = u < 0.8f;  out = keep ? v/0.8 : 0
__global__ void bn_dropout_kernel(float* __restrict__ out, int total)
{
    int t = blockIdx.x * blockDim.x + threadIdx.x;
    int i0 = t * 4;
    if (i0 >= total) return;
    float4 v = *(float4*)(out + i0);
    int c = i0 & 127;
    float4 sc = *(const float4*)(g_scale2 + c);
    float4 sh = *(const float4*)(g_shift2 + c);
    float vals[4] = { fmaf(v.x, sc.x, sh.x), fmaf(v.y, sc.y, sh.y),
                      fmaf(v.z, sc.z, sh.z), fmaf(v.w, sc.w, sh.w) };
    float res[4];
#pragma unroll
    for (int j = 0; j < 4; j++) {
        uint2 o = threefry2x32_042(0u, (uint32_t)(i0 + j));
        uint32_t bits = o.x ^ o.y;
        float u = __uint_as_float((bits >> 9) | 0x3f800000u) - 1.0f;
        res[j] = (u < 0.8f) ? vals[j] * 1.25f : 0.0f;
    }
    *(float4*)(out + i0) = make_float4(res[0], res[1], res[2], res[3]);
}

// ---------------- launch ----------------------------------------------------------
extern "C" void kernel_launch(void* const* d_in, const int* in_sizes, int n_in,
                              void* d_out, int out_size)
{
    const float* x      = (const float*)d_in[0];
    const void*  ei     = d_in[1];
    const float* ea     = (const float*)d_in[2];
    const float* W_edge = (const float*)d_in[3];
    const float* b_edge = (const float*)d_in[4];
    const float* epsp   = (const float*)d_in[5];
    const float* W1     = (const float*)d_in[6];
    const float* b1     = (const float*)d_in[7];
    const float* g1     = (const float*)d_in[8];
    const float* beta1  = (const float*)d_in[9];
    const float* W2     = (const float*)d_in[10];
    const float* b2     = (const float*)d_in[11];
    const float* g_o    = (const float*)d_in[12];
    const float* beta_o = (const float*)d_in[13];
    float* out = (float*)d_out;

    int M = in_sizes[0] / EMB;     // 50000
    int E = in_sizes[1] / 2;       // 800000
    float invM = 1.0f / (float)M;

    int nA = M * EMB;
    zero_kernel<<<(nA + 255) / 256, 256>>>(nA);
    detect_kernel<<<1, 1>>>((const unsigned long long*)ei, M);
    edge_kernel<<<(E + 7) / 8, 256>>>((const float4*)x, ei, ea,
                                      (const float4*)W_edge, (const float4*)b_edge, E);
    int gM = (M + 127) / 128;
    gemm1_kernel<<<dim3(gM, 2), 256>>>(x, W1, b1, epsp, M);
    stats1_kernel<<<(M + 255) / 256, 256>>>(M);
    finalize_kernel<<<1, 256>>>(g1, beta1, 0, invM);
    gemm2_kernel<<<dim3(gM, 1), 256>>>(W2, b2, out, M);
    stats2_kernel<<<(M + 255) / 256, 128>>>(out, M);
    finalize_kernel<<<1, 128>>>(g_o, beta_o, 1, invM);
    bn_dropout_kernel<<<(out_size / 4 + 255) / 256, 256>>>(out, out_size);
}